// round 1
// baseline (speedup 1.0000x reference)
#include <cuda_runtime.h>

// PartialSoftmaxDistiller: N=64 samples, C=1024 classes.
// loss = (1/N) * sum_i sum_{j: target[i,j]==1} KL( softmax_t(row_ij) || softmax_s(row_ij) )
// where row_ij = {negatives of sample i} U {j}.
//
// Closed form per sample i (maxes m_t, m_s over the full row for stability):
//   E_t = sum_{neg} exp(t-m_t); E_s = sum_{neg} exp(s-m_s);
//   A   = sum_{neg} exp(t-m_t)*(t-s)
//   KL_j = (A + e_t*(t_j-s_j))/(E_t+e_t) + (m_s+log(E_s+e_s)) - (m_t+log(E_t+e_t))
// with e_t=exp(t_j-m_t), e_s=exp(s_j-m_s).

#define NSAMP 64
#define NCLS  1024
#define NTHREADS 256   // 4 elements per thread via float4/int4

__device__ float g_partials[NSAMP];

__device__ __forceinline__ float warpMax(float v) {
    #pragma unroll
    for (int o = 16; o; o >>= 1) v = fmaxf(v, __shfl_xor_sync(0xffffffffu, v, o));
    return v;
}
__device__ __forceinline__ float warpSum(float v) {
    #pragma unroll
    for (int o = 16; o; o >>= 1) v += __shfl_xor_sync(0xffffffffu, v, o);
    return v;
}

__global__ void __launch_bounds__(NTHREADS)
pskd_main(const float* __restrict__ S,   // student [N, C]
          const float* __restrict__ T,   // teacher [N, C]
          const int*   __restrict__ G)   // target  [N, C]
{
    __shared__ float sm[3 * 8];   // per-warp partials (up to 3 concurrent reductions)
    __shared__ float bc[5];       // broadcast: m_t, m_s, E_t, E_s, A

    const int i    = blockIdx.x;
    const int tid  = threadIdx.x;
    const int wid  = tid >> 5;
    const int lane = tid & 31;

    const float4 sv = reinterpret_cast<const float4*>(S + i * NCLS)[tid];
    const float4 tv = reinterpret_cast<const float4*>(T + i * NCLS)[tid];
    const int4   gv = reinterpret_cast<const int4*>(G + i * NCLS)[tid];

    float sl[4] = {sv.x, sv.y, sv.z, sv.w};
    float tl[4] = {tv.x, tv.y, tv.z, tv.w};
    int   gl[4] = {gv.x, gv.y, gv.z, gv.w};

    // ---- row maxes (over all C; >= masked-row max, equally valid shift) ----
    float mt = -1e30f, ms = -1e30f;
    #pragma unroll
    for (int k = 0; k < 4; k++) { mt = fmaxf(mt, tl[k]); ms = fmaxf(ms, sl[k]); }
    mt = warpMax(mt);
    ms = warpMax(ms);
    if (lane == 0) { sm[wid] = mt; sm[8 + wid] = ms; }
    __syncthreads();
    if (tid == 0) {
        float a = sm[0], b = sm[8];
        #pragma unroll
        for (int k = 1; k < 8; k++) { a = fmaxf(a, sm[k]); b = fmaxf(b, sm[8 + k]); }
        bc[0] = a; bc[1] = b;
    }
    __syncthreads();
    mt = bc[0]; ms = bc[1];

    // ---- negative-set sums: E_t, E_s, A ----
    float et = 0.f, es = 0.f, av = 0.f;
    #pragma unroll
    for (int k = 0; k < 4; k++) {
        if (gl[k] == 0) {
            float e = expf(tl[k] - mt);
            et += e;
            es += expf(sl[k] - ms);
            av += e * (tl[k] - sl[k]);
        }
    }
    et = warpSum(et); es = warpSum(es); av = warpSum(av);
    __syncthreads();   // sm reuse: make sure max-phase reads are done
    if (lane == 0) { sm[wid] = et; sm[8 + wid] = es; sm[16 + wid] = av; }
    __syncthreads();
    if (tid == 0) {
        float a = 0.f, b = 0.f, c = 0.f;
        #pragma unroll
        for (int k = 0; k < 8; k++) { a += sm[k]; b += sm[8 + k]; c += sm[16 + k]; }
        bc[2] = a; bc[3] = b; bc[4] = c;
    }
    __syncthreads();
    const float Et = bc[2], Es = bc[3], A = bc[4];

    // ---- per-positive KL ----
    float kl = 0.f;
    #pragma unroll
    for (int k = 0; k < 4; k++) {
        if (gl[k] == 1) {
            float e_t = expf(tl[k] - mt);
            float e_s = expf(sl[k] - ms);
            float dt = Et + e_t;
            float ds = Es + e_s;
            kl += (A + e_t * (tl[k] - sl[k])) / dt
                + (ms + logf(ds)) - (mt + logf(dt));
        }
    }
    kl = warpSum(kl);
    __syncthreads();
    if (lane == 0) sm[wid] = kl;
    __syncthreads();
    if (tid == 0) {
        float v = 0.f;
        #pragma unroll
        for (int k = 0; k < 8; k++) v += sm[k];
        g_partials[i] = v;
    }
}

__global__ void __launch_bounds__(64)
pskd_finish(float* __restrict__ out)
{
    __shared__ float s2[2];
    const int tid = threadIdx.x;
    float v = g_partials[tid];           // 64 threads, one partial each
    v = warpSum(v);
    if ((tid & 31) == 0) s2[tid >> 5] = v;
    __syncthreads();
    if (tid == 0) out[0] = (s2[0] + s2[1]) * (1.0f / (float)NSAMP);
}

extern "C" void kernel_launch(void* const* d_in, const int* in_sizes, int n_in,
                              void* d_out, int out_size)
{
    const float* student = (const float*)d_in[0];
    const float* teacher = (const float*)d_in[1];
    const int*   target  = (const int*)d_in[2];
    float* out = (float*)d_out;

    pskd_main<<<NSAMP, NTHREADS>>>(student, teacher, target);
    pskd_finish<<<1, 64>>>(out);
}

// round 2
// speedup vs baseline: 1.0295x; 1.0295x over previous
#include <cuda_runtime.h>

// PartialSoftmaxDistiller: N=64 samples, C=1024 classes.
// loss = (1/N) * sum_i sum_{j: target[i,j]==1} KL( softmax_t(row_ij) || softmax_s(row_ij) )
// where row_ij = {negatives of sample i} U {j}.
//
// Closed form per sample i (maxes m_t, m_s over the full row for stability):
//   E_t = sum_{neg} exp(t-m_t); E_s = sum_{neg} exp(s-m_s);
//   A   = sum_{neg} exp(t-m_t)*(t-s)
//   KL_j = (A + e_t*(t_j-s_j))/(E_t+e_t) + (m_s+log(E_s+e_s)) - (m_t+log(E_t+e_t))
// with e_t=exp(t_j-m_t), e_s=exp(s_j-m_s).
//
// Single fused kernel: grid=64 blocks (one per sample); the block that draws
// the last atomic ticket reduces the 64 partials and writes the scalar loss,
// then resets the ticket counter so the launch is graph-replayable.

#define NSAMP 64
#define NCLS  1024
#define NTHREADS 256   // 4 elements per thread via float4/int4

__device__ float        g_partials[NSAMP];
__device__ unsigned int g_count = 0;

__device__ __forceinline__ float warpMax(float v) {
    #pragma unroll
    for (int o = 16; o; o >>= 1) v = fmaxf(v, __shfl_xor_sync(0xffffffffu, v, o));
    return v;
}
__device__ __forceinline__ float warpSum(float v) {
    #pragma unroll
    for (int o = 16; o; o >>= 1) v += __shfl_xor_sync(0xffffffffu, v, o);
    return v;
}

__global__ void __launch_bounds__(NTHREADS)
pskd_fused(const float* __restrict__ S,   // student [N, C]
           const float* __restrict__ T,   // teacher [N, C]
           const int*   __restrict__ G,   // target  [N, C]
           float* __restrict__ out)
{
    __shared__ float sm[3 * 8];   // per-warp partials (up to 3 concurrent reductions)
    __shared__ float bc[5];       // broadcast: m_t, m_s, E_t, E_s, A
    __shared__ float s2[2];
    __shared__ int   isLast;

    const int i    = blockIdx.x;
    const int tid  = threadIdx.x;
    const int wid  = tid >> 5;
    const int lane = tid & 31;

    const float4 sv = reinterpret_cast<const float4*>(S + i * NCLS)[tid];
    const float4 tv = reinterpret_cast<const float4*>(T + i * NCLS)[tid];
    const int4   gv = reinterpret_cast<const int4*>(G + i * NCLS)[tid];

    float sl[4] = {sv.x, sv.y, sv.z, sv.w};
    float tl[4] = {tv.x, tv.y, tv.z, tv.w};
    int   gl[4] = {gv.x, gv.y, gv.z, gv.w};

    // ---- row maxes (over all C; >= masked-row max, equally valid shift) ----
    float mt = -1e30f, ms = -1e30f;
    #pragma unroll
    for (int k = 0; k < 4; k++) { mt = fmaxf(mt, tl[k]); ms = fmaxf(ms, sl[k]); }
    mt = warpMax(mt);
    ms = warpMax(ms);
    if (lane == 0) { sm[wid] = mt; sm[8 + wid] = ms; }
    __syncthreads();
    if (tid == 0) {
        float a = sm[0], b = sm[8];
        #pragma unroll
        for (int k = 1; k < 8; k++) { a = fmaxf(a, sm[k]); b = fmaxf(b, sm[8 + k]); }
        bc[0] = a; bc[1] = b;
    }
    __syncthreads();
    mt = bc[0]; ms = bc[1];

    // ---- negative-set sums: E_t, E_s, A ----
    float et = 0.f, es = 0.f, av = 0.f;
    #pragma unroll
    for (int k = 0; k < 4; k++) {
        if (gl[k] == 0) {
            float e = __expf(tl[k] - mt);
            et += e;
            es += __expf(sl[k] - ms);
            av += e * (tl[k] - sl[k]);
        }
    }
    et = warpSum(et); es = warpSum(es); av = warpSum(av);
    __syncthreads();   // sm reuse: make sure max-phase reads are done
    if (lane == 0) { sm[wid] = et; sm[8 + wid] = es; sm[16 + wid] = av; }
    __syncthreads();
    if (tid == 0) {
        float a = 0.f, b = 0.f, c = 0.f;
        #pragma unroll
        for (int k = 0; k < 8; k++) { a += sm[k]; b += sm[8 + k]; c += sm[16 + k]; }
        bc[2] = a; bc[3] = b; bc[4] = c;
    }
    __syncthreads();
    const float Et = bc[2], Es = bc[3], A = bc[4];

    // ---- per-positive KL ----
    float kl = 0.f;
    #pragma unroll
    for (int k = 0; k < 4; k++) {
        if (gl[k] == 1) {
            float e_t = __expf(tl[k] - mt);
            float e_s = __expf(sl[k] - ms);
            float dt = Et + e_t;
            float ds = Es + e_s;
            kl += (A + e_t * (tl[k] - sl[k])) / dt
                + (ms + __logf(ds)) - (mt + __logf(dt));
        }
    }
    kl = warpSum(kl);
    __syncthreads();
    if (lane == 0) sm[wid] = kl;
    __syncthreads();
    if (tid == 0) {
        float v = 0.f;
        #pragma unroll
        for (int k = 0; k < 8; k++) v += sm[k];
        g_partials[i] = v;
        __threadfence();                       // make partial visible at L2
        unsigned int t = atomicAdd(&g_count, 1u);
        isLast = (t == NSAMP - 1) ? 1 : 0;
    }
    __syncthreads();

    // ---- last block: reduce 64 partials, write scalar, reset counter ----
    if (isLast) {
        if (tid < NSAMP) {
            float v = __ldcg(&g_partials[tid]);   // L2-coherent load
            v = warpSum(v);
            if ((tid & 31) == 0) s2[tid >> 5] = v;
        }
        __syncthreads();
        if (tid == 0) {
            out[0] = (s2[0] + s2[1]) * (1.0f / (float)NSAMP);
            g_count = 0;                          // reset for next graph replay
        }
    }
}

extern "C" void kernel_launch(void* const* d_in, const int* in_sizes, int n_in,
                              void* d_out, int out_size)
{
    const float* student = (const float*)d_in[0];
    const float* teacher = (const float*)d_in[1];
    const int*   target  = (const int*)d_in[2];
    float* out = (float*)d_out;

    pskd_fused<<<NSAMP, NTHREADS>>>(student, teacher, target, out);
}

// round 3
// speedup vs baseline: 1.0333x; 1.0037x over previous
#include <cuda_runtime.h>

// PartialSoftmaxDistiller: N=64 samples, C=1024 classes.
// loss = (1/N) * sum_i sum_{j: target[i,j]==1} KL( softmax_t(row_ij) || softmax_s(row_ij) )
// where row_ij = {negatives of sample i} U {j}.
//
// Per sample i (global maxes m_t, m_s):
//   E_t = sum_{neg} exp(t-m_t); E_s = sum_{neg} exp(s-m_s);
//   A   = sum_{neg} exp(t-m_t)*(t-s)
//   KL_j = (A + e_t*(t_j-s_j))/(E_t+e_t) + (m_s+log(E_s+e_s)) - (m_t+log(E_t+e_t))
//
// Warp-local stats with online-softmax merge (rescale by exp(m_w - m_global))
// avoid a dedicated block-wide max round. Single kernel; last atomic-ticket
// block (acq_rel, no threadfence) reduces the 64 partials and writes the loss.

#define NSAMP 64
#define NCLS  1024
#define NTHREADS 256
#define FULLM 0xffffffffu

__device__ float        g_partials[NSAMP];
__device__ unsigned int g_count = 0;

__device__ __forceinline__ float warpMax(float v) {
    #pragma unroll
    for (int o = 16; o; o >>= 1) v = fmaxf(v, __shfl_xor_sync(FULLM, v, o));
    return v;
}
__device__ __forceinline__ float warpSum(float v) {
    #pragma unroll
    for (int o = 16; o; o >>= 1) v += __shfl_xor_sync(FULLM, v, o);
    return v;
}

__global__ void __launch_bounds__(NTHREADS)
pskd_fused(const float* __restrict__ S,
           const float* __restrict__ T,
           const int*   __restrict__ G,
           float* __restrict__ out)
{
    __shared__ float sw[8][5];   // per-warp: m_t, m_s, E_t, E_s, A (reused for kl)
    __shared__ float bc[5];      // merged:   m_t, m_s, E_t, E_s, A
    __shared__ float s2[2];
    __shared__ int   isLast;

    const int i    = blockIdx.x;
    const int tid  = threadIdx.x;
    const int wid  = tid >> 5;
    const int lane = tid & 31;

    const float4 sv = reinterpret_cast<const float4*>(S + i * NCLS)[tid];
    const float4 tv = reinterpret_cast<const float4*>(T + i * NCLS)[tid];
    const int4   gv = reinterpret_cast<const int4*>(G + i * NCLS)[tid];

    float sl[4] = {sv.x, sv.y, sv.z, sv.w};
    float tl[4] = {tv.x, tv.y, tv.z, tv.w};
    int   gl[4] = {gv.x, gv.y, gv.z, gv.w};

    // ---- warp-local maxes ----
    float mt = fmaxf(fmaxf(tl[0], tl[1]), fmaxf(tl[2], tl[3]));
    float ms = fmaxf(fmaxf(sl[0], sl[1]), fmaxf(sl[2], sl[3]));
    mt = warpMax(mt);
    ms = warpMax(ms);

    // ---- warp-local negative-set sums (shifted by warp-local maxes) ----
    float et = 0.f, es = 0.f, av = 0.f;
    #pragma unroll
    for (int k = 0; k < 4; k++) {
        if (gl[k] == 0) {
            float e = __expf(tl[k] - mt);
            et += e;
            es += __expf(sl[k] - ms);
            av += e * (tl[k] - sl[k]);
        }
    }
    et = warpSum(et); es = warpSum(es); av = warpSum(av);

    if (lane == 0) {
        sw[wid][0] = mt; sw[wid][1] = ms;
        sw[wid][2] = et; sw[wid][3] = es; sw[wid][4] = av;
    }
    __syncthreads();

    // ---- warp 0 merges the 8 warp records (online-softmax rescale) ----
    if (wid == 0) {
        float wmt = -1e30f, wms = -1e30f, wet = 0.f, wes = 0.f, wav = 0.f;
        if (lane < 8) {
            wmt = sw[lane][0]; wms = sw[lane][1];
            wet = sw[lane][2]; wes = sw[lane][3]; wav = sw[lane][4];
        }
        float gmt = warpMax(wmt);
        float gms = warpMax(wms);
        float ft  = __expf(wmt - gmt);   // 0 for idle lanes (underflow)
        float fs  = __expf(wms - gms);
        float gEt = warpSum(wet * ft);
        float gEs = warpSum(wes * fs);
        float gA  = warpSum(wav * ft);
        if (lane == 0) {
            bc[0] = gmt; bc[1] = gms; bc[2] = gEt; bc[3] = gEs; bc[4] = gA;
        }
    }
    __syncthreads();
    const float gmt = bc[0], gms = bc[1], Et = bc[2], Es = bc[3], A = bc[4];

    // ---- per-positive KL ----
    float kl = 0.f;
    #pragma unroll
    for (int k = 0; k < 4; k++) {
        if (gl[k] == 1) {
            float e_t = __expf(tl[k] - gmt);
            float e_s = __expf(sl[k] - gms);
            float dt = Et + e_t;
            float ds = Es + e_s;
            kl += (A + e_t * (tl[k] - sl[k])) / dt
                + (gms + __logf(ds)) - (gmt + __logf(dt));
        }
    }
    kl = warpSum(kl);
    if (lane == 0) sw[wid][0] = kl;
    __syncthreads();

    if (tid == 0) {
        float v = 0.f;
        #pragma unroll
        for (int k = 0; k < 8; k++) v += sw[k][0];
        g_partials[i] = v;
        unsigned int t;
        // release: orders the partial STG; acquire: makes all partials
        // visible to the winning block. No MEMBAR.GPU / L1 flush.
        asm volatile("atom.add.acq_rel.gpu.u32 %0, [%1], %2;"
                     : "=r"(t) : "l"(&g_count), "r"(1u) : "memory");
        isLast = (t == NSAMP - 1) ? 1 : 0;
    }
    __syncthreads();

    // ---- last block: reduce 64 partials, write loss, reset counter ----
    if (isLast) {
        if (tid < NSAMP) {
            float v = __ldcg(&g_partials[tid]);
            v = warpSum(v);
            if ((tid & 31) == 0) s2[tid >> 5] = v;
        }
        __syncthreads();
        if (tid == 0) {
            out[0] = (s2[0] + s2[1]) * (1.0f / (float)NSAMP);
            g_count = 0;   // reset for next graph replay
        }
    }
}

extern "C" void kernel_launch(void* const* d_in, const int* in_sizes, int n_in,
                              void* d_out, int out_size)
{
    const float* student = (const float*)d_in[0];
    const float* teacher = (const float*)d_in[1];
    const int*   target  = (const int*)d_in[2];
    float* out = (float*)d_out;

    pskd_fused<<<NSAMP, NTHREADS>>>(student, teacher, target, out);
}